// round 13
// baseline (speedup 1.0000x reference)
#include <cuda_runtime.h>
#include <cuda_bf16.h>
#include <math_constants.h>
#include <cstdint>

#define N_FEAT 500000
#define DIM    768
#define NQ     64
#define TOPK   5
#define SEGLEN 512
#define M_TILE 64
#define KCH    64
#define NCHUNK (DIM / KCH)                 // 12
#define NBLK   ((N_FEAT + M_TILE - 1) / M_TILE)   // 7813
#define NSEL   8

#define SA_STRIDE 72

// ---------------- scratch ----------------
__device__ __align__(16) __nv_bfloat16 g_qb[NQ * DIM];
__device__ float g_bmax[(size_t)NQ * NBLK];   // 2MB
__device__ int   g_selblk[NQ * NSEL];
__device__ float g_cv[NQ * NSEL * TOPK];
__device__ int   g_ci[NQ * NSEL * TOPK];
__device__ int   g_top[NQ * TOPK];

__device__ __forceinline__ bool better(float av, int ai, float bv, int bi) {
    return (av > bv) || (av == bv && ai < bi);
}

__device__ __forceinline__ uint32_t smem_u32(const void* p) {
    return (uint32_t)__cvta_generic_to_shared(p);
}

__device__ __forceinline__ void mma16816(float& c0, float& c1, float& c2, float& c3,
                                         uint32_t a0, uint32_t a1, uint32_t a2, uint32_t a3,
                                         uint32_t b0, uint32_t b1) {
    asm volatile(
        "mma.sync.aligned.m16n8k16.row.col.f32.bf16.bf16.f32 "
        "{%0,%1,%2,%3}, {%4,%5,%6,%7}, {%8,%9}, {%0,%1,%2,%3};"
        : "+f"(c0), "+f"(c1), "+f"(c2), "+f"(c3)
        : "r"(a0), "r"(a1), "r"(a2), "r"(a3), "r"(b0), "r"(b1));
}

__device__ __forceinline__ void ldmatrix_x4(uint32_t& r0, uint32_t& r1, uint32_t& r2,
                                            uint32_t& r3, uint32_t addr) {
    asm volatile("ldmatrix.sync.aligned.m8n8.x4.shared.b16 {%0,%1,%2,%3}, [%4];"
                 : "=r"(r0), "=r"(r1), "=r"(r2), "=r"(r3) : "r"(addr));
}

// ---------------------------------------------------------------------------
// k0: queries fp32 -> bf16
// ---------------------------------------------------------------------------
__global__ void qconv_kernel(const float* __restrict__ qf) {
    int i = blockIdx.x * 256 + threadIdx.x;
    if (i < NQ * DIM / 2) {
        float2 f = ((const float2*)qf)[i];
        ((__nv_bfloat162*)g_qb)[i] = __float22bfloat162_rn(f);
    }
}

// ---------------------------------------------------------------------------
// k1: bf16 warp-MMA GEMM, tile 64 feat x 64 q (acc 16 regs/thread, bf16-
//     compressed A staging) -> 3 CTAs/SM (was 2) for deeper LDG overlap.
//     Warp tile 16 x 32 (4 m-groups x 2 n-groups).
// ---------------------------------------------------------------------------
__global__ __launch_bounds__(256, 3)
void mma_score_kernel(const float* __restrict__ ff, int blk_base) {
    __shared__ __nv_bfloat16 sa[2][M_TILE * SA_STRIDE];   // 2 x 9KB
    __shared__ __nv_bfloat16 sb[2][NQ * SA_STRIDE];       // 2 x 9KB
    __shared__ float snrm[M_TILE];
    __shared__ float swmax[4 * NQ];

    const int tid = threadIdx.x;
    const int wid = tid >> 5;
    const int lid = tid & 31;
    const int g   = lid >> 2;
    const int tg  = lid & 3;
    const int mg  = wid >> 1;          // m-group: rows mg*16..+15
    const int ng  = wid & 1;           // n-group: queries ng*32..+31
    const int blk = blk_base + blockIdx.x;
    const long n0 = (long)blk * M_TILE;

    const int mrow = (lid & 7) + ((lid >> 3) & 1) * 8;
    const int mcol = (lid >> 4) * 8;
    const uint32_t a_off = (uint32_t)(((mg * 16 + mrow) * SA_STRIDE + mcol) * 2);
    const int brow = (lid & 7) + (lid >> 4) * 8;
    const int bcol = ((lid >> 3) & 1) * 8;
    const uint32_t b_off = (uint32_t)(((ng * 32 + brow) * SA_STRIDE + bcol) * 2);
    const uint32_t sa_base0 = smem_u32(&sa[0][0]);
    const uint32_t sa_base1 = smem_u32(&sa[1][0]);
    const uint32_t sb_base0 = smem_u32(&sb[0][0]);
    const uint32_t sb_base1 = smem_u32(&sb[1][0]);

    float acc[4][4];                   // [nt][reg]
    #pragma unroll
    for (int nt = 0; nt < 4; nt++)
        #pragma unroll
        for (int r = 0; r < 4; r++) acc[nt][r] = 0.f;
    float npart[4] = {0.f, 0.f, 0.f, 0.f};

    uint2 ra[4];   // bf16-compressed A staging (8 regs)
    uint4 rb[2];

    // A: 64 rows x 64 cols fp32 = 1024 float4, 4/thread. Convert at load;
    // accumulate norm partials on the fp32 values before packing.
    auto ldg_chunk = [&](int c) {
        const int k0c = c * KCH;
        #pragma unroll
        for (int i = 0; i < 4; i++) {
            int id  = tid + 256 * i;
            int row = id >> 4;             // 0..63
            int j   = id & 15;
            long n  = n0 + row;
            float4 v = (n < N_FEAT) ? *(const float4*)&ff[n * (long)DIM + k0c + 4 * j]
                                    : make_float4(0.f, 0.f, 0.f, 0.f);
            npart[i] = fmaf(v.x, v.x, fmaf(v.y, v.y, fmaf(v.z, v.z, fmaf(v.w, v.w, npart[i]))));
            __nv_bfloat162 p0 = __float22bfloat162_rn(make_float2(v.x, v.y));
            __nv_bfloat162 p1 = __float22bfloat162_rn(make_float2(v.z, v.w));
            ra[i] = make_uint2(*(uint32_t*)&p0, *(uint32_t*)&p1);
        }
        #pragma unroll
        for (int i = 0; i < 2; i++) {
            int id  = tid + 256 * i;
            int row = id >> 3;
            int j   = id & 7;
            rb[i] = *(const uint4*)&g_qb[row * DIM + k0c + 8 * j];
        }
    };
    auto sts_chunk = [&](int buf) {
        #pragma unroll
        for (int i = 0; i < 4; i++) {
            int id  = tid + 256 * i;
            int row = id >> 4;
            int j   = id & 15;
            *(uint2*)&sa[buf][row * SA_STRIDE + 4 * j] = ra[i];
        }
        #pragma unroll
        for (int i = 0; i < 2; i++) {
            int id  = tid + 256 * i;
            int row = id >> 3;
            int j   = id & 7;
            *(uint4*)&sb[buf][row * SA_STRIDE + 8 * j] = rb[i];
        }
    };

    ldg_chunk(0);
    sts_chunk(0);
    if (NCHUNK > 1) ldg_chunk(1);
    __syncthreads();

    for (int c = 0; c < NCHUNK; c++) {
        if (c + 1 < NCHUNK) {
            sts_chunk((c + 1) & 1);
            if (c + 2 < NCHUNK) ldg_chunk(c + 2);
        }
        const uint32_t sabuf = (c & 1) ? sa_base1 : sa_base0;
        const uint32_t sbbuf = (c & 1) ? sb_base1 : sb_base0;

        #pragma unroll
        for (int ks = 0; ks < 4; ks++) {
            uint32_t a[4], b0[4], b1[4];
            ldmatrix_x4(a[0], a[1], a[2], a[3], sabuf + a_off + ks * 32);
            ldmatrix_x4(b0[0], b0[1], b0[2], b0[3], sbbuf + b_off + ks * 32);
            ldmatrix_x4(b1[0], b1[1], b1[2], b1[3], sbbuf + b_off + 2304u + ks * 32);
            mma16816(acc[0][0], acc[0][1], acc[0][2], acc[0][3],
                     a[0], a[1], a[2], a[3], b0[0], b0[1]);
            mma16816(acc[1][0], acc[1][1], acc[1][2], acc[1][3],
                     a[0], a[1], a[2], a[3], b0[2], b0[3]);
            mma16816(acc[2][0], acc[2][1], acc[2][2], acc[2][3],
                     a[0], a[1], a[2], a[3], b1[0], b1[1]);
            mma16816(acc[3][0], acc[3][1], acc[3][2], acc[3][3],
                     a[0], a[1], a[2], a[3], b1[2], b1[3]);
        }
        __syncthreads();
    }

    // norms: lanes 0-15 / 16-31 of each warp share 4 rows each
    #pragma unroll
    for (int i = 0; i < 4; i++) {
        float v = npart[i];
        v += __shfl_xor_sync(0xffffffffu, v, 1);
        v += __shfl_xor_sync(0xffffffffu, v, 2);
        v += __shfl_xor_sync(0xffffffffu, v, 4);
        v += __shfl_xor_sync(0xffffffffu, v, 8);
        if ((tid & 15) == 0) snrm[(tid >> 4) + 16 * i] = v;
    }
    __syncthreads();

    // per-(query,block) max of scaled scores
    {
        const int r0 = mg * 16 + g;
        float nr0 = snrm[r0], nr1 = snrm[r0 + 8];
        float s0 = (nr0 > 0.f) ? rsqrtf(nr0) : 0.f;
        float s1 = (nr1 > 0.f) ? rsqrtf(nr1) : 0.f;
        bool ok0 = (n0 + r0)     < N_FEAT;
        bool ok1 = (n0 + r0 + 8) < N_FEAT;
        #pragma unroll
        for (int nt = 0; nt < 4; nt++) {
            float v0 = fmaxf(ok0 ? acc[nt][0] * s0 : -CUDART_INF_F,
                             ok1 ? acc[nt][2] * s1 : -CUDART_INF_F);
            float v1 = fmaxf(ok0 ? acc[nt][1] * s0 : -CUDART_INF_F,
                             ok1 ? acc[nt][3] * s1 : -CUDART_INF_F);
            #pragma unroll
            for (int off = 4; off <= 16; off <<= 1) {
                v0 = fmaxf(v0, __shfl_xor_sync(0xffffffffu, v0, off));
                v1 = fmaxf(v1, __shfl_xor_sync(0xffffffffu, v1, off));
            }
            if (g == 0) {
                int q = ng * 32 + nt * 8 + 2 * tg;
                swmax[mg * NQ + q]     = v0;
                swmax[mg * NQ + q + 1] = v1;
            }
        }
    }
    __syncthreads();
    if (tid < NQ) {
        float m = swmax[tid];
        #pragma unroll
        for (int w = 1; w < 4; w++) m = fmaxf(m, swmax[w * NQ + tid]);
        g_bmax[(size_t)tid * NBLK + blk] = m;
    }
}

// ---------------------------------------------------------------------------
// k2: per query, top-8 blocks by approx max.
// ---------------------------------------------------------------------------
__global__ __launch_bounds__(256)
void select_kernel() {
    __shared__ float sval[NBLK];
    __shared__ float swv[8];  __shared__ int swi[8];

    const int q   = blockIdx.x;
    const int tid = threadIdx.x;
    const int wid = tid >> 5;
    const int lid = tid & 31;

    for (int b = tid; b < NBLK; b += 256)
        sval[b] = g_bmax[(size_t)q * NBLK + b];
    __syncthreads();

    for (int r = 0; r < NSEL; r++) {
        float bv = -CUDART_INF_F; int bi = 0x7fffffff;
        for (int b = tid; b < NBLK; b += 256)
            if (better(sval[b], b, bv, bi)) { bv = sval[b]; bi = b; }
        #pragma unroll
        for (int off = 16; off >= 1; off >>= 1) {
            float ov = __shfl_xor_sync(0xffffffffu, bv, off);
            int   oi = __shfl_xor_sync(0xffffffffu, bi, off);
            if (better(ov, oi, bv, bi)) { bv = ov; bi = oi; }
        }
        if (lid == 0) { swv[wid] = bv; swi[wid] = bi; }
        __syncthreads();
        if (tid == 0) {
            float mv = swv[0]; int mi = swi[0];
            #pragma unroll
            for (int w = 1; w < 8; w++)
                if (better(swv[w], swi[w], mv, mi)) { mv = swv[w]; mi = swi[w]; }
            g_selblk[q * NSEL + r] = mi;
            sval[mi] = -CUDART_INF_F;
        }
        __syncthreads();
    }
}

// ---------------------------------------------------------------------------
// k3: exact fp32 rescore; one block per (query, selected block).
// ---------------------------------------------------------------------------
__device__ __forceinline__ void insert5(float v, int idx, float tv[5], int ti[5]) {
    if (better(v, idx, tv[4], ti[4])) {
        tv[4] = v; ti[4] = idx;
        #pragma unroll
        for (int s = 4; s > 0; s--) {
            if (better(tv[s], ti[s], tv[s - 1], ti[s - 1])) {
                float fv = tv[s]; tv[s] = tv[s - 1]; tv[s - 1] = fv;
                int   fi = ti[s]; ti[s] = ti[s - 1]; ti[s - 1] = fi;
            }
        }
    }
}

__global__ __launch_bounds__(256)
void rescore_kernel(const float* __restrict__ qf, const float* __restrict__ ff) {
    __shared__ float wtv[8][TOPK]; __shared__ int wti[8][TOPK];

    const int b    = blockIdx.x;
    const int q    = b >> 3;
    const int slot = b & (NSEL - 1);
    const int wid  = threadIdx.x >> 5;
    const int lid  = threadIdx.x & 31;

    const long base = (long)g_selblk[q * NSEL + slot] * M_TILE;

    float tv[TOPK]; int ti[TOPK];
    #pragma unroll
    for (int s = 0; s < TOPK; s++) { tv[s] = -CUDART_INF_F; ti[s] = 0x7fffffff; }

    const float4* qr = (const float4*)&qf[q * DIM];
    for (int r = wid; r < M_TILE; r += 8) {
        long row = base + r;
        if (row < N_FEAT) {
            const float4* fr = (const float4*)&ff[row * (long)DIM];
            float dot = 0.f, nr = 0.f;
            #pragma unroll
            for (int u = 0; u < 6; u++) {
                float4 a = fr[lid + 32 * u];
                float4 bq = qr[lid + 32 * u];
                dot = fmaf(a.x, bq.x, fmaf(a.y, bq.y, fmaf(a.z, bq.z, fmaf(a.w, bq.w, dot))));
                nr  = fmaf(a.x, a.x, fmaf(a.y, a.y, fmaf(a.z, a.z, fmaf(a.w, a.w, nr))));
            }
            #pragma unroll
            for (int off = 16; off >= 1; off >>= 1) {
                dot += __shfl_xor_sync(0xffffffffu, dot, off);
                nr  += __shfl_xor_sync(0xffffffffu, nr,  off);
            }
            if (lid == 0)
                insert5(dot * rsqrtf(nr), (int)row, tv, ti);
        }
    }
    if (lid == 0) {
        #pragma unroll
        for (int s = 0; s < TOPK; s++) { wtv[wid][s] = tv[s]; wti[wid][s] = ti[s]; }
    }
    __syncthreads();

    if (threadIdx.x == 0) {
        float mv[TOPK]; int mi[TOPK];
        #pragma unroll
        for (int s = 0; s < TOPK; s++) { mv[s] = -CUDART_INF_F; mi[s] = 0x7fffffff; }
        for (int w = 0; w < 8; w++)
            #pragma unroll
            for (int s = 0; s < TOPK; s++)
                insert5(wtv[w][s], wti[w][s], mv, mi);
        #pragma unroll
        for (int s = 0; s < TOPK; s++) {
            g_cv[b * TOPK + s] = mv[s];
            g_ci[b * TOPK + s] = mi[s];
        }
    }
}

// ---------------------------------------------------------------------------
// k4: per query, merge NSEL*5 = 40 candidates -> final top-5.
// ---------------------------------------------------------------------------
__global__ void final_kernel() {
    const int q = threadIdx.x;
    if (q >= NQ) return;
    float tv[TOPK]; int ti[TOPK];
    #pragma unroll
    for (int s = 0; s < TOPK; s++) { tv[s] = -CUDART_INF_F; ti[s] = 0x7fffffff; }
    for (int e = 0; e < NSEL * TOPK; e++)
        insert5(g_cv[q * NSEL * TOPK + e], g_ci[q * NSEL * TOPK + e], tv, ti);
    #pragma unroll
    for (int s = 0; s < TOPK; s++)
        g_top[q * TOPK + s] = ti[s];
}

// ---------------------------------------------------------------------------
// k5: gather + int->float (output dtype float32).
// ---------------------------------------------------------------------------
__global__ __launch_bounds__(128)
void gather_kernel(const int* __restrict__ data, float* __restrict__ out) {
    const int r = blockIdx.x;
    int idx = g_top[r];
    idx = (idx < 0) ? 0 : ((idx >= N_FEAT) ? N_FEAT - 1 : idx);
    const int4* src = (const int4*)&data[(size_t)idx * SEGLEN];
    float4* dst = (float4*)&out[(size_t)r * SEGLEN];
    for (int t = threadIdx.x; t < SEGLEN / 4; t += blockDim.x) {
        int4 v = src[t];
        dst[t] = make_float4((float)v.x, (float)v.y, (float)v.z, (float)v.w);
    }
}

// ---------------------------------------------------------------------------
extern "C" void kernel_launch(void* const* d_in, const int* in_sizes, int n_in,
                              void* d_out, int out_size) {
    (void)out_size;
    int i_ff = 0, i_dt = -1, i_qf = -1;
    for (int i = 1; i < n_in; i++)
        if ((unsigned)in_sizes[i] > (unsigned)in_sizes[i_ff]) i_ff = i;
    for (int i = 0; i < n_in; i++) {
        if (i == i_ff) continue;
        if (i_dt < 0 || (unsigned)in_sizes[i] > (unsigned)in_sizes[i_dt]) i_dt = i;
    }
    for (int i = 0; i < n_in; i++) {
        if (i == i_ff || i == i_dt) continue;
        if (i_qf < 0 || (unsigned)in_sizes[i] > (unsigned)in_sizes[i_qf]) i_qf = i;
    }
    const float* qf   = (const float*)d_in[i_qf >= 0 ? i_qf : 0];
    const float* ff   = (const float*)d_in[i_ff];
    const int*   data = (const int*)d_in[i_dt >= 0 ? i_dt : (n_in > 2 ? 2 : 0)];
    float* out = (float*)d_out;

    qconv_kernel<<<(NQ * DIM / 2 + 255) / 256, 256>>>(qf);
    const int S = (NBLK + 3) / 4;   // 1954
    mma_score_kernel<<<S, 256>>>(ff, 0);
    mma_score_kernel<<<S, 256>>>(ff, S);
    mma_score_kernel<<<S, 256>>>(ff, 2 * S);
    mma_score_kernel<<<NBLK - 3 * S, 256>>>(ff, 3 * S);
    select_kernel<<<NQ, 256>>>();
    rescore_kernel<<<NQ * NSEL, 256>>>(qf, ff);
    final_kernel<<<1, NQ>>>();
    gather_kernel<<<NQ * TOPK, 128>>>(data, out);
}

// round 14
// speedup vs baseline: 1.0695x; 1.0695x over previous
#include <cuda_runtime.h>
#include <cuda_bf16.h>
#include <math_constants.h>
#include <cstdint>

#define N_FEAT 500000
#define DIM    768
#define NQ     64
#define TOPK   5
#define SEGLEN 512
#define M_TILE 128
#define KCH    64
#define NCHUNK (DIM / KCH)                 // 12
#define NBLK   ((N_FEAT + M_TILE - 1) / M_TILE)   // 3907
#define NSEL   8

#define SA_STRIDE 72

// ---------------- scratch ----------------
__device__ __align__(16) __nv_bfloat16 g_qb[NQ * DIM];
__device__ float g_bmax[(size_t)NQ * NBLK];
__device__ int   g_selblk[NQ * NSEL];
__device__ float g_cv[NQ * NSEL * TOPK];
__device__ int   g_ci[NQ * NSEL * TOPK];
__device__ int   g_top[NQ * TOPK];

__device__ __forceinline__ bool better(float av, int ai, float bv, int bi) {
    return (av > bv) || (av == bv && ai < bi);
}

__device__ __forceinline__ uint32_t smem_u32(const void* p) {
    return (uint32_t)__cvta_generic_to_shared(p);
}

__device__ __forceinline__ void mma16816(float& c0, float& c1, float& c2, float& c3,
                                         uint32_t a0, uint32_t a1, uint32_t a2, uint32_t a3,
                                         uint32_t b0, uint32_t b1) {
    asm volatile(
        "mma.sync.aligned.m16n8k16.row.col.f32.bf16.bf16.f32 "
        "{%0,%1,%2,%3}, {%4,%5,%6,%7}, {%8,%9}, {%0,%1,%2,%3};"
        : "+f"(c0), "+f"(c1), "+f"(c2), "+f"(c3)
        : "r"(a0), "r"(a1), "r"(a2), "r"(a3), "r"(b0), "r"(b1));
}

__device__ __forceinline__ void ldmatrix_x4(uint32_t& r0, uint32_t& r1, uint32_t& r2,
                                            uint32_t& r3, uint32_t addr) {
    asm volatile("ldmatrix.sync.aligned.m8n8.x4.shared.b16 {%0,%1,%2,%3}, [%4];"
                 : "=r"(r0), "=r"(r1), "=r"(r2), "=r"(r3) : "r"(addr));
}

// ---------------------------------------------------------------------------
// k0: queries fp32 -> bf16
// ---------------------------------------------------------------------------
__global__ void qconv_kernel(const float* __restrict__ qf) {
    int i = blockIdx.x * 256 + threadIdx.x;
    if (i < NQ * DIM / 2) {
        float2 f = ((const float2*)qf)[i];
        ((__nv_bfloat162*)g_qb)[i] = __float22bfloat162_rn(f);
    }
}

// ---------------------------------------------------------------------------
// k1: bf16 warp-MMA GEMM, 128 feat x 64 q tile (proven: 66% DRAM), with
//     (R14) bf16-compressed A staging (uint2[8], -16 regs) + occupancy 3
//     and single full-grid launch (kills 3 extra tail waves of the 4-slice
//     instrumentation split). Math bit-identical to R12.
// ---------------------------------------------------------------------------
__global__ __launch_bounds__(256, 3)
void mma_score_kernel(const float* __restrict__ ff) {
    __shared__ __nv_bfloat16 sa[2][M_TILE * SA_STRIDE];   // 2 x 18KB
    __shared__ __nv_bfloat16 sb[2][NQ * SA_STRIDE];       // 2 x 9KB
    __shared__ float snrm[M_TILE];
    __shared__ float swmax[4 * NQ];

    const int tid = threadIdx.x;
    const int wid = tid >> 5;
    const int lid = tid & 31;
    const int g   = lid >> 2;
    const int tg  = lid & 3;
    const int mg  = wid >> 1;
    const int ng  = wid & 1;
    const long n0 = (long)blockIdx.x * M_TILE;

    const int mrow = (lid & 7) + ((lid >> 3) & 1) * 8;
    const int mcol = (lid >> 4) * 8;
    const uint32_t a_off = (uint32_t)(((mg * 32 + mrow) * SA_STRIDE + mcol) * 2);
    const int brow = (lid & 7) + (lid >> 4) * 8;
    const int bcol = ((lid >> 3) & 1) * 8;
    const uint32_t b_off = (uint32_t)(((ng * 32 + brow) * SA_STRIDE + bcol) * 2);
    const uint32_t sa_base0 = smem_u32(&sa[0][0]);
    const uint32_t sa_base1 = smem_u32(&sa[1][0]);
    const uint32_t sb_base0 = smem_u32(&sb[0][0]);
    const uint32_t sb_base1 = smem_u32(&sb[1][0]);

    float acc[2][4][4];
    #pragma unroll
    for (int mt = 0; mt < 2; mt++)
        #pragma unroll
        for (int nt = 0; nt < 4; nt++)
            #pragma unroll
            for (int r = 0; r < 4; r++) acc[mt][nt][r] = 0.f;
    float npart[8] = {0.f, 0.f, 0.f, 0.f, 0.f, 0.f, 0.f, 0.f};

    uint2 ra[8];   // bf16-compressed A staging (16 regs, was 32)
    uint4 rb[2];

    auto ldg_chunk = [&](int c) {
        const int k0c = c * KCH;
        #pragma unroll
        for (int i = 0; i < 8; i++) {
            int id  = tid + 256 * i;
            int row = id >> 4;
            int j   = id & 15;
            long n  = n0 + row;
            float4 v = (n < N_FEAT) ? *(const float4*)&ff[n * (long)DIM + k0c + 4 * j]
                                    : make_float4(0.f, 0.f, 0.f, 0.f);
            npart[i] = fmaf(v.x, v.x, fmaf(v.y, v.y, fmaf(v.z, v.z, fmaf(v.w, v.w, npart[i]))));
            __nv_bfloat162 p0 = __float22bfloat162_rn(make_float2(v.x, v.y));
            __nv_bfloat162 p1 = __float22bfloat162_rn(make_float2(v.z, v.w));
            ra[i] = make_uint2(*(uint32_t*)&p0, *(uint32_t*)&p1);
        }
        #pragma unroll
        for (int i = 0; i < 2; i++) {
            int id  = tid + 256 * i;
            int row = id >> 3;
            int j   = id & 7;
            rb[i] = *(const uint4*)&g_qb[row * DIM + k0c + 8 * j];
        }
    };
    auto sts_chunk = [&](int buf) {
        #pragma unroll
        for (int i = 0; i < 8; i++) {
            int id  = tid + 256 * i;
            int row = id >> 4;
            int j   = id & 15;
            *(uint2*)&sa[buf][row * SA_STRIDE + 4 * j] = ra[i];
        }
        #pragma unroll
        for (int i = 0; i < 2; i++) {
            int id  = tid + 256 * i;
            int row = id >> 3;
            int j   = id & 7;
            *(uint4*)&sb[buf][row * SA_STRIDE + 8 * j] = rb[i];
        }
    };

    ldg_chunk(0);
    sts_chunk(0);
    if (NCHUNK > 1) ldg_chunk(1);
    __syncthreads();

    for (int c = 0; c < NCHUNK; c++) {
        if (c + 1 < NCHUNK) {
            sts_chunk((c + 1) & 1);
            if (c + 2 < NCHUNK) ldg_chunk(c + 2);
        }
        const uint32_t sabuf = (c & 1) ? sa_base1 : sa_base0;
        const uint32_t sbbuf = (c & 1) ? sb_base1 : sb_base0;

        #pragma unroll
        for (int ks = 0; ks < 4; ks++) {
            uint32_t a0[4], a1[4], b0[4], b1[4];
            ldmatrix_x4(a0[0], a0[1], a0[2], a0[3], sabuf + a_off + ks * 32);
            ldmatrix_x4(a1[0], a1[1], a1[2], a1[3], sabuf + a_off + 2304u + ks * 32);
            ldmatrix_x4(b0[0], b0[1], b0[2], b0[3], sbbuf + b_off + ks * 32);
            ldmatrix_x4(b1[0], b1[1], b1[2], b1[3], sbbuf + b_off + 2304u + ks * 32);
            #pragma unroll
            for (int mt = 0; mt < 2; mt++) {
                uint32_t* a = mt ? a1 : a0;
                mma16816(acc[mt][0][0], acc[mt][0][1], acc[mt][0][2], acc[mt][0][3],
                         a[0], a[1], a[2], a[3], b0[0], b0[1]);
                mma16816(acc[mt][1][0], acc[mt][1][1], acc[mt][1][2], acc[mt][1][3],
                         a[0], a[1], a[2], a[3], b0[2], b0[3]);
                mma16816(acc[mt][2][0], acc[mt][2][1], acc[mt][2][2], acc[mt][2][3],
                         a[0], a[1], a[2], a[3], b1[0], b1[1]);
                mma16816(acc[mt][3][0], acc[mt][3][1], acc[mt][3][2], acc[mt][3][3],
                         a[0], a[1], a[2], a[3], b1[2], b1[3]);
            }
        }
        __syncthreads();
    }

    #pragma unroll
    for (int i = 0; i < 8; i++) {
        float v = npart[i];
        v += __shfl_xor_sync(0xffffffffu, v, 1);
        v += __shfl_xor_sync(0xffffffffu, v, 2);
        v += __shfl_xor_sync(0xffffffffu, v, 4);
        v += __shfl_xor_sync(0xffffffffu, v, 8);
        if ((tid & 15) == 0) snrm[(tid >> 4) + 16 * i] = v;
    }
    __syncthreads();

    {
        float s[2][2];
        bool  ok[2][2];
        #pragma unroll
        for (int mt = 0; mt < 2; mt++) {
            int r0 = mg * 32 + mt * 16 + g;
            float nr0 = snrm[r0], nr1 = snrm[r0 + 8];
            s[mt][0] = (nr0 > 0.f) ? rsqrtf(nr0) : 0.f;
            s[mt][1] = (nr1 > 0.f) ? rsqrtf(nr1) : 0.f;
            ok[mt][0] = (n0 + r0)     < N_FEAT;
            ok[mt][1] = (n0 + r0 + 8) < N_FEAT;
        }
        #pragma unroll
        for (int nt = 0; nt < 4; nt++) {
            float v0 = -CUDART_INF_F, v1 = -CUDART_INF_F;
            #pragma unroll
            for (int mt = 0; mt < 2; mt++) {
                v0 = fmaxf(v0, fmaxf(ok[mt][0] ? acc[mt][nt][0] * s[mt][0] : -CUDART_INF_F,
                                     ok[mt][1] ? acc[mt][nt][2] * s[mt][1] : -CUDART_INF_F));
                v1 = fmaxf(v1, fmaxf(ok[mt][0] ? acc[mt][nt][1] * s[mt][0] : -CUDART_INF_F,
                                     ok[mt][1] ? acc[mt][nt][3] * s[mt][1] : -CUDART_INF_F));
            }
            #pragma unroll
            for (int off = 4; off <= 16; off <<= 1) {
                v0 = fmaxf(v0, __shfl_xor_sync(0xffffffffu, v0, off));
                v1 = fmaxf(v1, __shfl_xor_sync(0xffffffffu, v1, off));
            }
            if (g == 0) {
                int q = ng * 32 + nt * 8 + 2 * tg;
                swmax[mg * NQ + q]     = v0;
                swmax[mg * NQ + q + 1] = v1;
            }
        }
    }
    __syncthreads();
    if (tid < NQ) {
        float m = swmax[tid];
        #pragma unroll
        for (int w = 1; w < 4; w++) m = fmaxf(m, swmax[w * NQ + tid]);
        g_bmax[(size_t)tid * NBLK + blockIdx.x] = m;
    }
}

// ---------------------------------------------------------------------------
// k2: per query, top-8 blocks by approx max.
// ---------------------------------------------------------------------------
__global__ __launch_bounds__(256)
void select_kernel() {
    __shared__ float sval[NBLK];
    __shared__ float swv[8];  __shared__ int swi[8];

    const int q   = blockIdx.x;
    const int tid = threadIdx.x;
    const int wid = tid >> 5;
    const int lid = tid & 31;

    for (int b = tid; b < NBLK; b += 256)
        sval[b] = g_bmax[(size_t)q * NBLK + b];
    __syncthreads();

    for (int r = 0; r < NSEL; r++) {
        float bv = -CUDART_INF_F; int bi = 0x7fffffff;
        for (int b = tid; b < NBLK; b += 256)
            if (better(sval[b], b, bv, bi)) { bv = sval[b]; bi = b; }
        #pragma unroll
        for (int off = 16; off >= 1; off >>= 1) {
            float ov = __shfl_xor_sync(0xffffffffu, bv, off);
            int   oi = __shfl_xor_sync(0xffffffffu, bi, off);
            if (better(ov, oi, bv, bi)) { bv = ov; bi = oi; }
        }
        if (lid == 0) { swv[wid] = bv; swi[wid] = bi; }
        __syncthreads();
        if (tid == 0) {
            float mv = swv[0]; int mi = swi[0];
            #pragma unroll
            for (int w = 1; w < 8; w++)
                if (better(swv[w], swi[w], mv, mi)) { mv = swv[w]; mi = swi[w]; }
            g_selblk[q * NSEL + r] = mi;
            sval[mi] = -CUDART_INF_F;
        }
        __syncthreads();
    }
}

// ---------------------------------------------------------------------------
// k3: exact fp32 rescore; one block per (query, selected block).
// ---------------------------------------------------------------------------
__device__ __forceinline__ void insert5(float v, int idx, float tv[5], int ti[5]) {
    if (better(v, idx, tv[4], ti[4])) {
        tv[4] = v; ti[4] = idx;
        #pragma unroll
        for (int s = 4; s > 0; s--) {
            if (better(tv[s], ti[s], tv[s - 1], ti[s - 1])) {
                float fv = tv[s]; tv[s] = tv[s - 1]; tv[s - 1] = fv;
                int   fi = ti[s]; ti[s] = ti[s - 1]; ti[s - 1] = fi;
            }
        }
    }
}

__global__ __launch_bounds__(256)
void rescore_kernel(const float* __restrict__ qf, const float* __restrict__ ff) {
    __shared__ float wtv[8][TOPK]; __shared__ int wti[8][TOPK];

    const int b    = blockIdx.x;
    const int q    = b >> 3;
    const int slot = b & (NSEL - 1);
    const int wid  = threadIdx.x >> 5;
    const int lid  = threadIdx.x & 31;

    const long base = (long)g_selblk[q * NSEL + slot] * M_TILE;

    float tv[TOPK]; int ti[TOPK];
    #pragma unroll
    for (int s = 0; s < TOPK; s++) { tv[s] = -CUDART_INF_F; ti[s] = 0x7fffffff; }

    const float4* qr = (const float4*)&qf[q * DIM];
    for (int r = wid; r < M_TILE; r += 8) {
        long row = base + r;
        if (row < N_FEAT) {
            const float4* fr = (const float4*)&ff[row * (long)DIM];
            float dot = 0.f, nr = 0.f;
            #pragma unroll
            for (int u = 0; u < 6; u++) {
                float4 a = fr[lid + 32 * u];
                float4 bq = qr[lid + 32 * u];
                dot = fmaf(a.x, bq.x, fmaf(a.y, bq.y, fmaf(a.z, bq.z, fmaf(a.w, bq.w, dot))));
                nr  = fmaf(a.x, a.x, fmaf(a.y, a.y, fmaf(a.z, a.z, fmaf(a.w, a.w, nr))));
            }
            #pragma unroll
            for (int off = 16; off >= 1; off >>= 1) {
                dot += __shfl_xor_sync(0xffffffffu, dot, off);
                nr  += __shfl_xor_sync(0xffffffffu, nr,  off);
            }
            if (lid == 0)
                insert5(dot * rsqrtf(nr), (int)row, tv, ti);
        }
    }
    if (lid == 0) {
        #pragma unroll
        for (int s = 0; s < TOPK; s++) { wtv[wid][s] = tv[s]; wti[wid][s] = ti[s]; }
    }
    __syncthreads();

    if (threadIdx.x == 0) {
        float mv[TOPK]; int mi[TOPK];
        #pragma unroll
        for (int s = 0; s < TOPK; s++) { mv[s] = -CUDART_INF_F; mi[s] = 0x7fffffff; }
        for (int w = 0; w < 8; w++)
            #pragma unroll
            for (int s = 0; s < TOPK; s++)
                insert5(wtv[w][s], wti[w][s], mv, mi);
        #pragma unroll
        for (int s = 0; s < TOPK; s++) {
            g_cv[b * TOPK + s] = mv[s];
            g_ci[b * TOPK + s] = mi[s];
        }
    }
}

// ---------------------------------------------------------------------------
// k4: per query, merge NSEL*5 = 40 candidates -> final top-5.
// ---------------------------------------------------------------------------
__global__ void final_kernel() {
    const int q = threadIdx.x;
    if (q >= NQ) return;
    float tv[TOPK]; int ti[TOPK];
    #pragma unroll
    for (int s = 0; s < TOPK; s++) { tv[s] = -CUDART_INF_F; ti[s] = 0x7fffffff; }
    for (int e = 0; e < NSEL * TOPK; e++)
        insert5(g_cv[q * NSEL * TOPK + e], g_ci[q * NSEL * TOPK + e], tv, ti);
    #pragma unroll
    for (int s = 0; s < TOPK; s++)
        g_top[q * TOPK + s] = ti[s];
}

// ---------------------------------------------------------------------------
// k5: gather + int->float (output dtype float32).
// ---------------------------------------------------------------------------
__global__ __launch_bounds__(128)
void gather_kernel(const int* __restrict__ data, float* __restrict__ out) {
    const int r = blockIdx.x;
    int idx = g_top[r];
    idx = (idx < 0) ? 0 : ((idx >= N_FEAT) ? N_FEAT - 1 : idx);
    const int4* src = (const int4*)&data[(size_t)idx * SEGLEN];
    float4* dst = (float4*)&out[(size_t)r * SEGLEN];
    for (int t = threadIdx.x; t < SEGLEN / 4; t += blockDim.x) {
        int4 v = src[t];
        dst[t] = make_float4((float)v.x, (float)v.y, (float)v.z, (float)v.w);
    }
}

// ---------------------------------------------------------------------------
extern "C" void kernel_launch(void* const* d_in, const int* in_sizes, int n_in,
                              void* d_out, int out_size) {
    (void)out_size;
    int i_ff = 0, i_dt = -1, i_qf = -1;
    for (int i = 1; i < n_in; i++)
        if ((unsigned)in_sizes[i] > (unsigned)in_sizes[i_ff]) i_ff = i;
    for (int i = 0; i < n_in; i++) {
        if (i == i_ff) continue;
        if (i_dt < 0 || (unsigned)in_sizes[i] > (unsigned)in_sizes[i_dt]) i_dt = i;
    }
    for (int i = 0; i < n_in; i++) {
        if (i == i_ff || i == i_dt) continue;
        if (i_qf < 0 || (unsigned)in_sizes[i] > (unsigned)in_sizes[i_qf]) i_qf = i;
    }
    const float* qf   = (const float*)d_in[i_qf >= 0 ? i_qf : 0];
    const float* ff   = (const float*)d_in[i_ff];
    const int*   data = (const int*)d_in[i_dt >= 0 ? i_dt : (n_in > 2 ? 2 : 0)];
    float* out = (float*)d_out;

    qconv_kernel<<<(NQ * DIM / 2 + 255) / 256, 256>>>(qf);
    mma_score_kernel<<<NBLK, 256>>>(ff);          // single launch: one tail wave
    select_kernel<<<NQ, 256>>>();
    rescore_kernel<<<NQ * NSEL, 256>>>(qf, ff);
    final_kernel<<<1, NQ>>>();
    gather_kernel<<<NQ * TOPK, 128>>>(data, out);
}

// round 15
// speedup vs baseline: 1.1716x; 1.0955x over previous
#include <cuda_runtime.h>
#include <cuda_bf16.h>
#include <math_constants.h>
#include <cstdint>

#define N_FEAT 500000
#define DIM    768
#define NQ     64
#define TOPK   5
#define SEGLEN 512
#define M_TILE 128
#define SUB    32                          // selection granularity (rows)
#define KCH    64
#define NCHUNK (DIM / KCH)                 // 12
#define NBLK   ((N_FEAT + M_TILE - 1) / M_TILE)   // 3907
#define NSUB   (NBLK * 4)                  // 15628 32-row subblocks
#define NSEL   8

#define SA_STRIDE 72

// ---------------- scratch ----------------
__device__ __align__(16) __nv_bfloat16 g_qb[NQ * DIM];
__device__ float g_bmax[(size_t)NQ * NSUB];   // per (query, 32-row subblock) max, 4MB
__device__ int   g_selblk[NQ * NSEL];
__device__ float g_cv[NQ * NSEL * TOPK];
__device__ int   g_ci[NQ * NSEL * TOPK];
__device__ int   g_top[NQ * TOPK];

__device__ __forceinline__ bool better(float av, int ai, float bv, int bi) {
    return (av > bv) || (av == bv && ai < bi);
}

__device__ __forceinline__ uint32_t smem_u32(const void* p) {
    return (uint32_t)__cvta_generic_to_shared(p);
}

__device__ __forceinline__ void mma16816(float& c0, float& c1, float& c2, float& c3,
                                         uint32_t a0, uint32_t a1, uint32_t a2, uint32_t a3,
                                         uint32_t b0, uint32_t b1) {
    asm volatile(
        "mma.sync.aligned.m16n8k16.row.col.f32.bf16.bf16.f32 "
        "{%0,%1,%2,%3}, {%4,%5,%6,%7}, {%8,%9}, {%0,%1,%2,%3};"
        : "+f"(c0), "+f"(c1), "+f"(c2), "+f"(c3)
        : "r"(a0), "r"(a1), "r"(a2), "r"(a3), "r"(b0), "r"(b1));
}

__device__ __forceinline__ void ldmatrix_x4(uint32_t& r0, uint32_t& r1, uint32_t& r2,
                                            uint32_t& r3, uint32_t addr) {
    asm volatile("ldmatrix.sync.aligned.m8n8.x4.shared.b16 {%0,%1,%2,%3}, [%4];"
                 : "=r"(r0), "=r"(r1), "=r"(r2), "=r"(r3) : "r"(addr));
}

// ---------------------------------------------------------------------------
// k0: queries fp32 -> bf16
// ---------------------------------------------------------------------------
__global__ void qconv_kernel(const float* __restrict__ qf) {
    int i = blockIdx.x * 256 + threadIdx.x;
    if (i < NQ * DIM / 2) {
        float2 f = ((const float2*)qf)[i];
        ((__nv_bfloat162*)g_qb)[i] = __float22bfloat162_rn(f);
    }
}

// ---------------------------------------------------------------------------
// k1: R12-proven GEMM internals (float4 staging, regs ~126, 2 CTAs/SM),
//     single full-grid launch; epilogue publishes per-32-row subblock maxes
//     (they were already computed as swmax[mg] — just not reduced away).
// ---------------------------------------------------------------------------
__global__ __launch_bounds__(256)
void mma_score_kernel(const float* __restrict__ ff) {
    __shared__ __nv_bfloat16 sa[2][M_TILE * SA_STRIDE];
    __shared__ __nv_bfloat16 sb[2][NQ * SA_STRIDE];
    __shared__ float snrm[M_TILE];
    __shared__ float swmax[4 * NQ];

    const int tid = threadIdx.x;
    const int wid = tid >> 5;
    const int lid = tid & 31;
    const int g   = lid >> 2;
    const int tg  = lid & 3;
    const int mg  = wid >> 1;
    const int ng  = wid & 1;
    const long n0 = (long)blockIdx.x * M_TILE;

    const int mrow = (lid & 7) + ((lid >> 3) & 1) * 8;
    const int mcol = (lid >> 4) * 8;
    const uint32_t a_off = (uint32_t)(((mg * 32 + mrow) * SA_STRIDE + mcol) * 2);
    const int brow = (lid & 7) + (lid >> 4) * 8;
    const int bcol = ((lid >> 3) & 1) * 8;
    const uint32_t b_off = (uint32_t)(((ng * 32 + brow) * SA_STRIDE + bcol) * 2);
    const uint32_t sa_base0 = smem_u32(&sa[0][0]);
    const uint32_t sa_base1 = smem_u32(&sa[1][0]);
    const uint32_t sb_base0 = smem_u32(&sb[0][0]);
    const uint32_t sb_base1 = smem_u32(&sb[1][0]);

    float acc[2][4][4];
    #pragma unroll
    for (int mt = 0; mt < 2; mt++)
        #pragma unroll
        for (int nt = 0; nt < 4; nt++)
            #pragma unroll
            for (int r = 0; r < 4; r++) acc[mt][nt][r] = 0.f;
    float npart[8] = {0.f, 0.f, 0.f, 0.f, 0.f, 0.f, 0.f, 0.f};

    float4 ra[8];
    uint4  rb[2];

    auto ldg_chunk = [&](int c) {
        const int k0c = c * KCH;
        #pragma unroll
        for (int i = 0; i < 8; i++) {
            int id  = tid + 256 * i;
            int row = id >> 4;
            int j   = id & 15;
            long n  = n0 + row;
            ra[i] = (n < N_FEAT) ? *(const float4*)&ff[n * (long)DIM + k0c + 4 * j]
                                 : make_float4(0.f, 0.f, 0.f, 0.f);
        }
        #pragma unroll
        for (int i = 0; i < 2; i++) {
            int id  = tid + 256 * i;
            int row = id >> 3;
            int j   = id & 7;
            rb[i] = *(const uint4*)&g_qb[row * DIM + k0c + 8 * j];
        }
    };
    auto sts_chunk = [&](int buf) {
        #pragma unroll
        for (int i = 0; i < 8; i++) {
            int id  = tid + 256 * i;
            int row = id >> 4;
            int j   = id & 15;
            float4 v = ra[i];
            npart[i] = fmaf(v.x, v.x, fmaf(v.y, v.y, fmaf(v.z, v.z, fmaf(v.w, v.w, npart[i]))));
            __nv_bfloat162 p0 = __float22bfloat162_rn(make_float2(v.x, v.y));
            __nv_bfloat162 p1 = __float22bfloat162_rn(make_float2(v.z, v.w));
            *(uint2*)&sa[buf][row * SA_STRIDE + 4 * j] =
                make_uint2(*(uint32_t*)&p0, *(uint32_t*)&p1);
        }
        #pragma unroll
        for (int i = 0; i < 2; i++) {
            int id  = tid + 256 * i;
            int row = id >> 3;
            int j   = id & 7;
            *(uint4*)&sb[buf][row * SA_STRIDE + 8 * j] = rb[i];
        }
    };

    ldg_chunk(0);
    sts_chunk(0);
    if (NCHUNK > 1) ldg_chunk(1);
    __syncthreads();

    for (int c = 0; c < NCHUNK; c++) {
        if (c + 1 < NCHUNK) {
            sts_chunk((c + 1) & 1);
            if (c + 2 < NCHUNK) ldg_chunk(c + 2);
        }
        const uint32_t sabuf = (c & 1) ? sa_base1 : sa_base0;
        const uint32_t sbbuf = (c & 1) ? sb_base1 : sb_base0;

        #pragma unroll
        for (int ks = 0; ks < 4; ks++) {
            uint32_t a0[4], a1[4], b0[4], b1[4];
            ldmatrix_x4(a0[0], a0[1], a0[2], a0[3], sabuf + a_off + ks * 32);
            ldmatrix_x4(a1[0], a1[1], a1[2], a1[3], sabuf + a_off + 2304u + ks * 32);
            ldmatrix_x4(b0[0], b0[1], b0[2], b0[3], sbbuf + b_off + ks * 32);
            ldmatrix_x4(b1[0], b1[1], b1[2], b1[3], sbbuf + b_off + 2304u + ks * 32);
            #pragma unroll
            for (int mt = 0; mt < 2; mt++) {
                uint32_t* a = mt ? a1 : a0;
                mma16816(acc[mt][0][0], acc[mt][0][1], acc[mt][0][2], acc[mt][0][3],
                         a[0], a[1], a[2], a[3], b0[0], b0[1]);
                mma16816(acc[mt][1][0], acc[mt][1][1], acc[mt][1][2], acc[mt][1][3],
                         a[0], a[1], a[2], a[3], b0[2], b0[3]);
                mma16816(acc[mt][2][0], acc[mt][2][1], acc[mt][2][2], acc[mt][2][3],
                         a[0], a[1], a[2], a[3], b1[0], b1[1]);
                mma16816(acc[mt][3][0], acc[mt][3][1], acc[mt][3][2], acc[mt][3][3],
                         a[0], a[1], a[2], a[3], b1[2], b1[3]);
            }
        }
        __syncthreads();
    }

    #pragma unroll
    for (int i = 0; i < 8; i++) {
        float v = npart[i];
        v += __shfl_xor_sync(0xffffffffu, v, 1);
        v += __shfl_xor_sync(0xffffffffu, v, 2);
        v += __shfl_xor_sync(0xffffffffu, v, 4);
        v += __shfl_xor_sync(0xffffffffu, v, 8);
        if ((tid & 15) == 0) snrm[(tid >> 4) + 16 * i] = v;
    }
    __syncthreads();

    {
        float s[2][2];
        bool  ok[2][2];
        #pragma unroll
        for (int mt = 0; mt < 2; mt++) {
            int r0 = mg * 32 + mt * 16 + g;
            float nr0 = snrm[r0], nr1 = snrm[r0 + 8];
            s[mt][0] = (nr0 > 0.f) ? rsqrtf(nr0) : 0.f;
            s[mt][1] = (nr1 > 0.f) ? rsqrtf(nr1) : 0.f;
            ok[mt][0] = (n0 + r0)     < N_FEAT;
            ok[mt][1] = (n0 + r0 + 8) < N_FEAT;
        }
        #pragma unroll
        for (int nt = 0; nt < 4; nt++) {
            float v0 = -CUDART_INF_F, v1 = -CUDART_INF_F;
            #pragma unroll
            for (int mt = 0; mt < 2; mt++) {
                v0 = fmaxf(v0, fmaxf(ok[mt][0] ? acc[mt][nt][0] * s[mt][0] : -CUDART_INF_F,
                                     ok[mt][1] ? acc[mt][nt][2] * s[mt][1] : -CUDART_INF_F));
                v1 = fmaxf(v1, fmaxf(ok[mt][0] ? acc[mt][nt][1] * s[mt][0] : -CUDART_INF_F,
                                     ok[mt][1] ? acc[mt][nt][3] * s[mt][1] : -CUDART_INF_F));
            }
            #pragma unroll
            for (int off = 4; off <= 16; off <<= 1) {
                v0 = fmaxf(v0, __shfl_xor_sync(0xffffffffu, v0, off));
                v1 = fmaxf(v1, __shfl_xor_sync(0xffffffffu, v1, off));
            }
            if (g == 0) {
                int q = ng * 32 + nt * 8 + 2 * tg;
                swmax[mg * NQ + q]     = v0;   // max over 32 rows mg*32..+31
                swmax[mg * NQ + q + 1] = v1;
            }
        }
    }
    __syncthreads();
    // publish per-32-row subblock maxes: subid = blk*4 + mg
    if (tid < 4 * NQ) {
        int q  = tid >> 2;
        int m4 = tid & 3;
        g_bmax[(size_t)q * NSUB + blockIdx.x * 4 + m4] = swmax[m4 * NQ + q];
    }
}

// ---------------------------------------------------------------------------
// k2: per query, top-8 32-row subblocks (8 argmax rounds over gmem, L2-hot;
// skip-list of already-selected).
// ---------------------------------------------------------------------------
__global__ __launch_bounds__(256)
void select_kernel() {
    __shared__ float swv[8];  __shared__ int swi[8];
    __shared__ int   sel[NSEL];

    const int q   = blockIdx.x;
    const int tid = threadIdx.x;
    const int wid = tid >> 5;
    const int lid = tid & 31;
    const float* row = &g_bmax[(size_t)q * NSUB];

    for (int r = 0; r < NSEL; r++) {
        float bv = -CUDART_INF_F; int bi = 0x7fffffff;
        for (int b = tid; b < NSUB; b += 256) {
            bool skip = false;
            for (int s = 0; s < r; s++) skip |= (sel[s] == b);
            float v = row[b];
            if (!skip && better(v, b, bv, bi)) { bv = v; bi = b; }
        }
        #pragma unroll
        for (int off = 16; off >= 1; off >>= 1) {
            float ov = __shfl_xor_sync(0xffffffffu, bv, off);
            int   oi = __shfl_xor_sync(0xffffffffu, bi, off);
            if (better(ov, oi, bv, bi)) { bv = ov; bi = oi; }
        }
        if (lid == 0) { swv[wid] = bv; swi[wid] = bi; }
        __syncthreads();
        if (tid == 0) {
            float mv = swv[0]; int mi = swi[0];
            #pragma unroll
            for (int w = 1; w < 8; w++)
                if (better(swv[w], swi[w], mv, mi)) { mv = swv[w]; mi = swi[w]; }
            sel[r] = mi;
            g_selblk[q * NSEL + r] = mi;
        }
        __syncthreads();
    }
}

// ---------------------------------------------------------------------------
// k3: exact fp32 rescore; one block per (query, selected 32-row subblock).
// ---------------------------------------------------------------------------
__device__ __forceinline__ void insert5(float v, int idx, float tv[5], int ti[5]) {
    if (better(v, idx, tv[4], ti[4])) {
        tv[4] = v; ti[4] = idx;
        #pragma unroll
        for (int s = 4; s > 0; s--) {
            if (better(tv[s], ti[s], tv[s - 1], ti[s - 1])) {
                float fv = tv[s]; tv[s] = tv[s - 1]; tv[s - 1] = fv;
                int   fi = ti[s]; ti[s] = ti[s - 1]; ti[s - 1] = fi;
            }
        }
    }
}

__global__ __launch_bounds__(256)
void rescore_kernel(const float* __restrict__ qf, const float* __restrict__ ff) {
    __shared__ float wtv[8][TOPK]; __shared__ int wti[8][TOPK];

    const int b    = blockIdx.x;
    const int q    = b >> 3;
    const int slot = b & (NSEL - 1);
    const int wid  = threadIdx.x >> 5;
    const int lid  = threadIdx.x & 31;

    const long base = (long)g_selblk[q * NSEL + slot] * SUB;

    float tv[TOPK]; int ti[TOPK];
    #pragma unroll
    for (int s = 0; s < TOPK; s++) { tv[s] = -CUDART_INF_F; ti[s] = 0x7fffffff; }

    const float4* qr = (const float4*)&qf[q * DIM];
    #pragma unroll
    for (int it = 0; it < SUB / 8; it++) {          // 4 rows per warp
        long row = base + wid + 8 * it;
        if (row < N_FEAT) {
            const float4* fr = (const float4*)&ff[row * (long)DIM];
            float dot = 0.f, nr = 0.f;
            #pragma unroll
            for (int u = 0; u < 6; u++) {
                float4 a = fr[lid + 32 * u];
                float4 bq = qr[lid + 32 * u];
                dot = fmaf(a.x, bq.x, fmaf(a.y, bq.y, fmaf(a.z, bq.z, fmaf(a.w, bq.w, dot))));
                nr  = fmaf(a.x, a.x, fmaf(a.y, a.y, fmaf(a.z, a.z, fmaf(a.w, a.w, nr))));
            }
            #pragma unroll
            for (int off = 16; off >= 1; off >>= 1) {
                dot += __shfl_xor_sync(0xffffffffu, dot, off);
                nr  += __shfl_xor_sync(0xffffffffu, nr,  off);
            }
            if (lid == 0)
                insert5(dot * rsqrtf(nr), (int)row, tv, ti);
        }
    }
    if (lid == 0) {
        #pragma unroll
        for (int s = 0; s < TOPK; s++) { wtv[wid][s] = tv[s]; wti[wid][s] = ti[s]; }
    }
    __syncthreads();

    if (threadIdx.x == 0) {
        float mv[TOPK]; int mi[TOPK];
        #pragma unroll
        for (int s = 0; s < TOPK; s++) { mv[s] = -CUDART_INF_F; mi[s] = 0x7fffffff; }
        for (int w = 0; w < 8; w++)
            #pragma unroll
            for (int s = 0; s < TOPK; s++)
                insert5(wtv[w][s], wti[w][s], mv, mi);
        #pragma unroll
        for (int s = 0; s < TOPK; s++) {
            g_cv[b * TOPK + s] = mv[s];
            g_ci[b * TOPK + s] = mi[s];
        }
    }
}

// ---------------------------------------------------------------------------
// k4: per query, merge NSEL*5 = 40 candidates -> final top-5.
// ---------------------------------------------------------------------------
__global__ void final_kernel() {
    const int q = threadIdx.x;
    if (q >= NQ) return;
    float tv[TOPK]; int ti[TOPK];
    #pragma unroll
    for (int s = 0; s < TOPK; s++) { tv[s] = -CUDART_INF_F; ti[s] = 0x7fffffff; }
    for (int e = 0; e < NSEL * TOPK; e++)
        insert5(g_cv[q * NSEL * TOPK + e], g_ci[q * NSEL * TOPK + e], tv, ti);
    #pragma unroll
    for (int s = 0; s < TOPK; s++)
        g_top[q * TOPK + s] = ti[s];
}

// ---------------------------------------------------------------------------
// k5: gather + int->float (output dtype float32).
// ---------------------------------------------------------------------------
__global__ __launch_bounds__(128)
void gather_kernel(const int* __restrict__ data, float* __restrict__ out) {
    const int r = blockIdx.x;
    int idx = g_top[r];
    idx = (idx < 0) ? 0 : ((idx >= N_FEAT) ? N_FEAT - 1 : idx);
    const int4* src = (const int4*)&data[(size_t)idx * SEGLEN];
    float4* dst = (float4*)&out[(size_t)r * SEGLEN];
    for (int t = threadIdx.x; t < SEGLEN / 4; t += blockDim.x) {
        int4 v = src[t];
        dst[t] = make_float4((float)v.x, (float)v.y, (float)v.z, (float)v.w);
    }
}

// ---------------------------------------------------------------------------
extern "C" void kernel_launch(void* const* d_in, const int* in_sizes, int n_in,
                              void* d_out, int out_size) {
    (void)out_size;
    int i_ff = 0, i_dt = -1, i_qf = -1;
    for (int i = 1; i < n_in; i++)
        if ((unsigned)in_sizes[i] > (unsigned)in_sizes[i_ff]) i_ff = i;
    for (int i = 0; i < n_in; i++) {
        if (i == i_ff) continue;
        if (i_dt < 0 || (unsigned)in_sizes[i] > (unsigned)in_sizes[i_dt]) i_dt = i;
    }
    for (int i = 0; i < n_in; i++) {
        if (i == i_ff || i == i_dt) continue;
        if (i_qf < 0 || (unsigned)in_sizes[i] > (unsigned)in_sizes[i_qf]) i_qf = i;
    }
    const float* qf   = (const float*)d_in[i_qf >= 0 ? i_qf : 0];
    const float* ff   = (const float*)d_in[i_ff];
    const int*   data = (const int*)d_in[i_dt >= 0 ? i_dt : (n_in > 2 ? 2 : 0)];
    float* out = (float*)d_out;

    qconv_kernel<<<(NQ * DIM / 2 + 255) / 256, 256>>>(qf);
    mma_score_kernel<<<NBLK, 256>>>(ff);
    select_kernel<<<NQ, 256>>>();
    rescore_kernel<<<NQ * NSEL, 256>>>(qf, ff);
    final_kernel<<<1, NQ>>>();
    gather_kernel<<<NQ * TOPK, 128>>>(data, out);
}

// round 16
// speedup vs baseline: 1.3119x; 1.1198x over previous
#include <cuda_runtime.h>
#include <cuda_bf16.h>
#include <math_constants.h>
#include <cstdint>

#define N_FEAT 500000
#define DIM    768
#define NQ     64
#define TOPK   5
#define SEGLEN 512
#define M_TILE 128
#define SUB    32
#define KCH    64
#define NCHUNK (DIM / KCH)                 // 12
#define NBLK   ((N_FEAT + M_TILE - 1) / M_TILE)   // 3907
#define NSUB   (NBLK * 4)                  // 15628
#define NSEL   8

#define SA_STRIDE 72

// ---------------- scratch ----------------
__device__ __align__(16) __nv_bfloat16 g_qb[NQ * DIM];
__device__ float g_bmax[(size_t)NQ * NSUB];
__device__ int   g_selblk[NQ * NSEL];
__device__ float g_cv[NQ * NSEL * TOPK];
__device__ int   g_ci[NQ * NSEL * TOPK];

__device__ __forceinline__ bool better(float av, int ai, float bv, int bi) {
    return (av > bv) || (av == bv && ai < bi);
}

__device__ __forceinline__ uint32_t smem_u32(const void* p) {
    return (uint32_t)__cvta_generic_to_shared(p);
}

__device__ __forceinline__ void mma16816(float& c0, float& c1, float& c2, float& c3,
                                         uint32_t a0, uint32_t a1, uint32_t a2, uint32_t a3,
                                         uint32_t b0, uint32_t b1) {
    asm volatile(
        "mma.sync.aligned.m16n8k16.row.col.f32.bf16.bf16.f32 "
        "{%0,%1,%2,%3}, {%4,%5,%6,%7}, {%8,%9}, {%0,%1,%2,%3};"
        : "+f"(c0), "+f"(c1), "+f"(c2), "+f"(c3)
        : "r"(a0), "r"(a1), "r"(a2), "r"(a3), "r"(b0), "r"(b1));
}

__device__ __forceinline__ void ldmatrix_x4(uint32_t& r0, uint32_t& r1, uint32_t& r2,
                                            uint32_t& r3, uint32_t addr) {
    asm volatile("ldmatrix.sync.aligned.m8n8.x4.shared.b16 {%0,%1,%2,%3}, [%4];"
                 : "=r"(r0), "=r"(r1), "=r"(r2), "=r"(r3) : "r"(addr));
}

// ---------------------------------------------------------------------------
// k0: queries fp32 -> bf16
// ---------------------------------------------------------------------------
__global__ void qconv_kernel(const float* __restrict__ qf) {
    int i = blockIdx.x * 256 + threadIdx.x;
    if (i < NQ * DIM / 2) {
        float2 f = ((const float2*)qf)[i];
        ((__nv_bfloat162*)g_qb)[i] = __float22bfloat162_rn(f);
    }
}

// ---------------------------------------------------------------------------
// k1: R12/R15-proven bf16 warp-MMA GEMM — UNCHANGED from R15.
// ---------------------------------------------------------------------------
__global__ __launch_bounds__(256)
void mma_score_kernel(const float* __restrict__ ff) {
    __shared__ __nv_bfloat16 sa[2][M_TILE * SA_STRIDE];
    __shared__ __nv_bfloat16 sb[2][NQ * SA_STRIDE];
    __shared__ float snrm[M_TILE];
    __shared__ float swmax[4 * NQ];

    const int tid = threadIdx.x;
    const int wid = tid >> 5;
    const int lid = tid & 31;
    const int g   = lid >> 2;
    const int tg  = lid & 3;
    const int mg  = wid >> 1;
    const int ng  = wid & 1;
    const long n0 = (long)blockIdx.x * M_TILE;

    const int mrow = (lid & 7) + ((lid >> 3) & 1) * 8;
    const int mcol = (lid >> 4) * 8;
    const uint32_t a_off = (uint32_t)(((mg * 32 + mrow) * SA_STRIDE + mcol) * 2);
    const int brow = (lid & 7) + (lid >> 4) * 8;
    const int bcol = ((lid >> 3) & 1) * 8;
    const uint32_t b_off = (uint32_t)(((ng * 32 + brow) * SA_STRIDE + bcol) * 2);
    const uint32_t sa_base0 = smem_u32(&sa[0][0]);
    const uint32_t sa_base1 = smem_u32(&sa[1][0]);
    const uint32_t sb_base0 = smem_u32(&sb[0][0]);
    const uint32_t sb_base1 = smem_u32(&sb[1][0]);

    float acc[2][4][4];
    #pragma unroll
    for (int mt = 0; mt < 2; mt++)
        #pragma unroll
        for (int nt = 0; nt < 4; nt++)
            #pragma unroll
            for (int r = 0; r < 4; r++) acc[mt][nt][r] = 0.f;
    float npart[8] = {0.f, 0.f, 0.f, 0.f, 0.f, 0.f, 0.f, 0.f};

    float4 ra[8];
    uint4  rb[2];

    auto ldg_chunk = [&](int c) {
        const int k0c = c * KCH;
        #pragma unroll
        for (int i = 0; i < 8; i++) {
            int id  = tid + 256 * i;
            int row = id >> 4;
            int j   = id & 15;
            long n  = n0 + row;
            ra[i] = (n < N_FEAT) ? *(const float4*)&ff[n * (long)DIM + k0c + 4 * j]
                                 : make_float4(0.f, 0.f, 0.f, 0.f);
        }
        #pragma unroll
        for (int i = 0; i < 2; i++) {
            int id  = tid + 256 * i;
            int row = id >> 3;
            int j   = id & 7;
            rb[i] = *(const uint4*)&g_qb[row * DIM + k0c + 8 * j];
        }
    };
    auto sts_chunk = [&](int buf) {
        #pragma unroll
        for (int i = 0; i < 8; i++) {
            int id  = tid + 256 * i;
            int row = id >> 4;
            int j   = id & 15;
            float4 v = ra[i];
            npart[i] = fmaf(v.x, v.x, fmaf(v.y, v.y, fmaf(v.z, v.z, fmaf(v.w, v.w, npart[i]))));
            __nv_bfloat162 p0 = __float22bfloat162_rn(make_float2(v.x, v.y));
            __nv_bfloat162 p1 = __float22bfloat162_rn(make_float2(v.z, v.w));
            *(uint2*)&sa[buf][row * SA_STRIDE + 4 * j] =
                make_uint2(*(uint32_t*)&p0, *(uint32_t*)&p1);
        }
        #pragma unroll
        for (int i = 0; i < 2; i++) {
            int id  = tid + 256 * i;
            int row = id >> 3;
            int j   = id & 7;
            *(uint4*)&sb[buf][row * SA_STRIDE + 8 * j] = rb[i];
        }
    };

    ldg_chunk(0);
    sts_chunk(0);
    if (NCHUNK > 1) ldg_chunk(1);
    __syncthreads();

    for (int c = 0; c < NCHUNK; c++) {
        if (c + 1 < NCHUNK) {
            sts_chunk((c + 1) & 1);
            if (c + 2 < NCHUNK) ldg_chunk(c + 2);
        }
        const uint32_t sabuf = (c & 1) ? sa_base1 : sa_base0;
        const uint32_t sbbuf = (c & 1) ? sb_base1 : sb_base0;

        #pragma unroll
        for (int ks = 0; ks < 4; ks++) {
            uint32_t a0[4], a1[4], b0[4], b1[4];
            ldmatrix_x4(a0[0], a0[1], a0[2], a0[3], sabuf + a_off + ks * 32);
            ldmatrix_x4(a1[0], a1[1], a1[2], a1[3], sabuf + a_off + 2304u + ks * 32);
            ldmatrix_x4(b0[0], b0[1], b0[2], b0[3], sbbuf + b_off + ks * 32);
            ldmatrix_x4(b1[0], b1[1], b1[2], b1[3], sbbuf + b_off + 2304u + ks * 32);
            #pragma unroll
            for (int mt = 0; mt < 2; mt++) {
                uint32_t* a = mt ? a1 : a0;
                mma16816(acc[mt][0][0], acc[mt][0][1], acc[mt][0][2], acc[mt][0][3],
                         a[0], a[1], a[2], a[3], b0[0], b0[1]);
                mma16816(acc[mt][1][0], acc[mt][1][1], acc[mt][1][2], acc[mt][1][3],
                         a[0], a[1], a[2], a[3], b0[2], b0[3]);
                mma16816(acc[mt][2][0], acc[mt][2][1], acc[mt][2][2], acc[mt][2][3],
                         a[0], a[1], a[2], a[3], b1[0], b1[1]);
                mma16816(acc[mt][3][0], acc[mt][3][1], acc[mt][3][2], acc[mt][3][3],
                         a[0], a[1], a[2], a[3], b1[2], b1[3]);
            }
        }
        __syncthreads();
    }

    #pragma unroll
    for (int i = 0; i < 8; i++) {
        float v = npart[i];
        v += __shfl_xor_sync(0xffffffffu, v, 1);
        v += __shfl_xor_sync(0xffffffffu, v, 2);
        v += __shfl_xor_sync(0xffffffffu, v, 4);
        v += __shfl_xor_sync(0xffffffffu, v, 8);
        if ((tid & 15) == 0) snrm[(tid >> 4) + 16 * i] = v;
    }
    __syncthreads();

    {
        float s[2][2];
        bool  ok[2][2];
        #pragma unroll
        for (int mt = 0; mt < 2; mt++) {
            int r0 = mg * 32 + mt * 16 + g;
            float nr0 = snrm[r0], nr1 = snrm[r0 + 8];
            s[mt][0] = (nr0 > 0.f) ? rsqrtf(nr0) : 0.f;
            s[mt][1] = (nr1 > 0.f) ? rsqrtf(nr1) : 0.f;
            ok[mt][0] = (n0 + r0)     < N_FEAT;
            ok[mt][1] = (n0 + r0 + 8) < N_FEAT;
        }
        #pragma unroll
        for (int nt = 0; nt < 4; nt++) {
            float v0 = -CUDART_INF_F, v1 = -CUDART_INF_F;
            #pragma unroll
            for (int mt = 0; mt < 2; mt++) {
                v0 = fmaxf(v0, fmaxf(ok[mt][0] ? acc[mt][nt][0] * s[mt][0] : -CUDART_INF_F,
                                     ok[mt][1] ? acc[mt][nt][2] * s[mt][1] : -CUDART_INF_F));
                v1 = fmaxf(v1, fmaxf(ok[mt][0] ? acc[mt][nt][1] * s[mt][0] : -CUDART_INF_F,
                                     ok[mt][1] ? acc[mt][nt][3] * s[mt][1] : -CUDART_INF_F));
            }
            #pragma unroll
            for (int off = 4; off <= 16; off <<= 1) {
                v0 = fmaxf(v0, __shfl_xor_sync(0xffffffffu, v0, off));
                v1 = fmaxf(v1, __shfl_xor_sync(0xffffffffu, v1, off));
            }
            if (g == 0) {
                int q = ng * 32 + nt * 8 + 2 * tg;
                swmax[mg * NQ + q]     = v0;
                swmax[mg * NQ + q + 1] = v1;
            }
        }
    }
    __syncthreads();
    if (tid < 4 * NQ) {
        int q  = tid >> 2;
        int m4 = tid & 3;
        g_bmax[(size_t)q * NSUB + blockIdx.x * 4 + m4] = swmax[m4 * NQ + q];
    }
}

// ---------------------------------------------------------------------------
// k2: per query, top-8 subblocks — ONE pass (per-thread sorted 8-list +
// 256->1 tree merge; structure proven in R8), replacing 8 serialized scans.
// ---------------------------------------------------------------------------
__device__ __forceinline__ void insert8(float v, int idx, float tv[NSEL], int ti[NSEL]) {
    if (better(v, idx, tv[NSEL - 1], ti[NSEL - 1])) {
        tv[NSEL - 1] = v; ti[NSEL - 1] = idx;
        #pragma unroll
        for (int s = NSEL - 1; s > 0; s--) {
            if (better(tv[s], ti[s], tv[s - 1], ti[s - 1])) {
                float fv = tv[s]; tv[s] = tv[s - 1]; tv[s - 1] = fv;
                int   fi = ti[s]; ti[s] = ti[s - 1]; ti[s - 1] = fi;
            }
        }
    }
}

__global__ __launch_bounds__(256)
void select_kernel() {
    const int q   = blockIdx.x;
    const int tid = threadIdx.x;

    float tv[NSEL]; int ti[NSEL];
    #pragma unroll
    for (int s = 0; s < NSEL; s++) { tv[s] = -CUDART_INF_F; ti[s] = 0x7fffffff; }

    const float* row = &g_bmax[(size_t)q * NSUB];
    for (int b = tid; b < NSUB; b += 256)
        insert8(row[b], b, tv, ti);

    __shared__ float sv[256 * NSEL];
    __shared__ int   si[256 * NSEL];
    #pragma unroll
    for (int s = 0; s < NSEL; s++) { sv[tid * NSEL + s] = tv[s]; si[tid * NSEL + s] = ti[s]; }
    __syncthreads();

    for (int off = 128; off >= 1; off >>= 1) {
        if (tid < off) {
            float ov[NSEL]; int oi[NSEL];
            #pragma unroll
            for (int s = 0; s < NSEL; s++) {
                ov[s] = sv[(tid + off) * NSEL + s];
                oi[s] = si[(tid + off) * NSEL + s];
            }
            float mv[NSEL]; int mi[NSEL];
            int a = 0, b = 0;
            #pragma unroll
            for (int o = 0; o < NSEL; o++) {
                if (better(tv[a], ti[a], ov[b], oi[b])) { mv[o] = tv[a]; mi[o] = ti[a]; a++; }
                else                                    { mv[o] = ov[b]; mi[o] = oi[b]; b++; }
            }
            #pragma unroll
            for (int s = 0; s < NSEL; s++) {
                tv[s] = mv[s]; ti[s] = mi[s];
                sv[tid * NSEL + s] = mv[s];
                si[tid * NSEL + s] = mi[s];
            }
        }
        __syncthreads();
    }

    if (tid == 0) {
        #pragma unroll
        for (int s = 0; s < NSEL; s++) g_selblk[q * NSEL + s] = ti[s];
    }
}

// ---------------------------------------------------------------------------
// k3: exact fp32 rescore; one block per (query, selected 32-row subblock)
// — UNCHANGED from R15.
// ---------------------------------------------------------------------------
__device__ __forceinline__ void insert5(float v, int idx, float tv[5], int ti[5]) {
    if (better(v, idx, tv[4], ti[4])) {
        tv[4] = v; ti[4] = idx;
        #pragma unroll
        for (int s = 4; s > 0; s--) {
            if (better(tv[s], ti[s], tv[s - 1], ti[s - 1])) {
                float fv = tv[s]; tv[s] = tv[s - 1]; tv[s - 1] = fv;
                int   fi = ti[s]; ti[s] = ti[s - 1]; ti[s - 1] = fi;
            }
        }
    }
}

__global__ __launch_bounds__(256)
void rescore_kernel(const float* __restrict__ qf, const float* __restrict__ ff) {
    __shared__ float wtv[8][TOPK]; __shared__ int wti[8][TOPK];

    const int b    = blockIdx.x;
    const int q    = b >> 3;
    const int slot = b & (NSEL - 1);
    const int wid  = threadIdx.x >> 5;
    const int lid  = threadIdx.x & 31;

    const long base = (long)g_selblk[q * NSEL + slot] * SUB;

    float tv[TOPK]; int ti[TOPK];
    #pragma unroll
    for (int s = 0; s < TOPK; s++) { tv[s] = -CUDART_INF_F; ti[s] = 0x7fffffff; }

    const float4* qr = (const float4*)&qf[q * DIM];
    #pragma unroll
    for (int it = 0; it < SUB / 8; it++) {
        long row = base + wid + 8 * it;
        if (row < N_FEAT) {
            const float4* fr = (const float4*)&ff[row * (long)DIM];
            float dot = 0.f, nr = 0.f;
            #pragma unroll
            for (int u = 0; u < 6; u++) {
                float4 a = fr[lid + 32 * u];
                float4 bq = qr[lid + 32 * u];
                dot = fmaf(a.x, bq.x, fmaf(a.y, bq.y, fmaf(a.z, bq.z, fmaf(a.w, bq.w, dot))));
                nr  = fmaf(a.x, a.x, fmaf(a.y, a.y, fmaf(a.z, a.z, fmaf(a.w, a.w, nr))));
            }
            #pragma unroll
            for (int off = 16; off >= 1; off >>= 1) {
                dot += __shfl_xor_sync(0xffffffffu, dot, off);
                nr  += __shfl_xor_sync(0xffffffffu, nr,  off);
            }
            if (lid == 0)
                insert5(dot * rsqrtf(nr), (int)row, tv, ti);
        }
    }
    if (lid == 0) {
        #pragma unroll
        for (int s = 0; s < TOPK; s++) { wtv[wid][s] = tv[s]; wti[wid][s] = ti[s]; }
    }
    __syncthreads();

    if (threadIdx.x == 0) {
        float mv[TOPK]; int mi[TOPK];
        #pragma unroll
        for (int s = 0; s < TOPK; s++) { mv[s] = -CUDART_INF_F; mi[s] = 0x7fffffff; }
        for (int w = 0; w < 8; w++)
            #pragma unroll
            for (int s = 0; s < TOPK; s++)
                insert5(wtv[w][s], wti[w][s], mv, mi);
        #pragma unroll
        for (int s = 0; s < TOPK; s++) {
            g_cv[b * TOPK + s] = mv[s];
            g_ci[b * TOPK + s] = mi[s];
        }
    }
}

// ---------------------------------------------------------------------------
// k4: gather, with inlined final top-5 (block r = q*5 + j picks rank j from
// the 40 candidates itself — removes the separate final_kernel launch).
// ---------------------------------------------------------------------------
__global__ __launch_bounds__(128)
void gather_kernel(const int* __restrict__ data, float* __restrict__ out) {
    __shared__ int s_idx;
    const int r = blockIdx.x;
    const int q = r / TOPK;
    const int j = r % TOPK;

    if (threadIdx.x == 0) {
        float tv[TOPK]; int ti[TOPK];
        #pragma unroll
        for (int s = 0; s < TOPK; s++) { tv[s] = -CUDART_INF_F; ti[s] = 0x7fffffff; }
        for (int e = 0; e < NSEL * TOPK; e++)
            insert5(g_cv[q * NSEL * TOPK + e], g_ci[q * NSEL * TOPK + e], tv, ti);
        int idx = ti[j];
        s_idx = (idx < 0) ? 0 : ((idx >= N_FEAT) ? N_FEAT - 1 : idx);
    }
    __syncthreads();

    const int idx = s_idx;
    const int4* src = (const int4*)&data[(size_t)idx * SEGLEN];
    float4* dst = (float4*)&out[(size_t)r * SEGLEN];
    for (int t = threadIdx.x; t < SEGLEN / 4; t += blockDim.x) {
        int4 v = src[t];
        dst[t] = make_float4((float)v.x, (float)v.y, (float)v.z, (float)v.w);
    }
}

// ---------------------------------------------------------------------------
extern "C" void kernel_launch(void* const* d_in, const int* in_sizes, int n_in,
                              void* d_out, int out_size) {
    (void)out_size;
    int i_ff = 0, i_dt = -1, i_qf = -1;
    for (int i = 1; i < n_in; i++)
        if ((unsigned)in_sizes[i] > (unsigned)in_sizes[i_ff]) i_ff = i;
    for (int i = 0; i < n_in; i++) {
        if (i == i_ff) continue;
        if (i_dt < 0 || (unsigned)in_sizes[i] > (unsigned)in_sizes[i_dt]) i_dt = i;
    }
    for (int i = 0; i < n_in; i++) {
        if (i == i_ff || i == i_dt) continue;
        if (i_qf < 0 || (unsigned)in_sizes[i] > (unsigned)in_sizes[i_qf]) i_qf = i;
    }
    const float* qf   = (const float*)d_in[i_qf >= 0 ? i_qf : 0];
    const float* ff   = (const float*)d_in[i_ff];
    const int*   data = (const int*)d_in[i_dt >= 0 ? i_dt : (n_in > 2 ? 2 : 0)];
    float* out = (float*)d_out;

    qconv_kernel<<<(NQ * DIM / 2 + 255) / 256, 256>>>(qf);
    mma_score_kernel<<<NBLK, 256>>>(ff);
    select_kernel<<<NQ, 256>>>();
    rescore_kernel<<<NQ * NSEL, 256>>>(qf, ff);
    gather_kernel<<<NQ * TOPK, 128>>>(data, out);
}

// round 17
// speedup vs baseline: 1.3143x; 1.0018x over previous
#include <cuda_runtime.h>
#include <cuda_bf16.h>
#include <math_constants.h>
#include <cstdint>

#define N_FEAT 500000
#define DIM    768
#define NQ     64
#define TOPK   5
#define SEGLEN 512
#define M_TILE 128
#define SUB    32
#define KCH    64
#define NCHUNK (DIM / KCH)                 // 12
#define NBLK   ((N_FEAT + M_TILE - 1) / M_TILE)   // 3907
#define NSUB   (NBLK * 4)                  // 15628
#define NSEL   8

#define SA_STRIDE 72

// ---------------- scratch ----------------
__device__ __align__(16) __nv_bfloat16 g_qb[NQ * DIM];
__device__ float g_bmax[(size_t)NQ * NSUB];
__device__ int   g_selblk[NQ * NSEL];
__device__ float g_cv[NQ * NSEL * TOPK];
__device__ int   g_ci[NQ * NSEL * TOPK];

__device__ __forceinline__ bool better(float av, int ai, float bv, int bi) {
    return (av > bv) || (av == bv && ai < bi);
}

__device__ __forceinline__ uint32_t smem_u32(const void* p) {
    return (uint32_t)__cvta_generic_to_shared(p);
}

__device__ __forceinline__ void mma16816(float& c0, float& c1, float& c2, float& c3,
                                         uint32_t a0, uint32_t a1, uint32_t a2, uint32_t a3,
                                         uint32_t b0, uint32_t b1) {
    asm volatile(
        "mma.sync.aligned.m16n8k16.row.col.f32.bf16.bf16.f32 "
        "{%0,%1,%2,%3}, {%4,%5,%6,%7}, {%8,%9}, {%0,%1,%2,%3};"
        : "+f"(c0), "+f"(c1), "+f"(c2), "+f"(c3)
        : "r"(a0), "r"(a1), "r"(a2), "r"(a3), "r"(b0), "r"(b1));
}

__device__ __forceinline__ void ldmatrix_x4(uint32_t& r0, uint32_t& r1, uint32_t& r2,
                                            uint32_t& r3, uint32_t addr) {
    asm volatile("ldmatrix.sync.aligned.m8n8.x4.shared.b16 {%0,%1,%2,%3}, [%4];"
                 : "=r"(r0), "=r"(r1), "=r"(r2), "=r"(r3) : "r"(addr));
}

// ---------------------------------------------------------------------------
// k0: queries fp32 -> bf16
// ---------------------------------------------------------------------------
__global__ void qconv_kernel(const float* __restrict__ qf) {
    int i = blockIdx.x * 256 + threadIdx.x;
    if (i < NQ * DIM / 2) {
        float2 f = ((const float2*)qf)[i];
        ((__nv_bfloat162*)g_qb)[i] = __float22bfloat162_rn(f);
    }
}

// ---------------------------------------------------------------------------
// k1: bf16 warp-MMA GEMM — identical to R16 EXCEPT the redundant mid-chunk
//     __syncthreads is removed (true single-sync double buffer):
//     MMA(c) reads buf[c&1]; sts(c+1) writes buf[(c+1)&1] (disjoint);
//     the WAR hazard (sts(c+2) vs MMA(c) on buf[c&1]) is covered by the
//     single end-of-iteration sync. STS/LDG now overlap the MMA phase.
// ---------------------------------------------------------------------------
__global__ __launch_bounds__(256)
void mma_score_kernel(const float* __restrict__ ff) {
    __shared__ __nv_bfloat16 sa[2][M_TILE * SA_STRIDE];
    __shared__ __nv_bfloat16 sb[2][NQ * SA_STRIDE];
    __shared__ float snrm[M_TILE];
    __shared__ float swmax[4 * NQ];

    const int tid = threadIdx.x;
    const int wid = tid >> 5;
    const int lid = tid & 31;
    const int g   = lid >> 2;
    const int tg  = lid & 3;
    const int mg  = wid >> 1;
    const int ng  = wid & 1;
    const long n0 = (long)blockIdx.x * M_TILE;

    const int mrow = (lid & 7) + ((lid >> 3) & 1) * 8;
    const int mcol = (lid >> 4) * 8;
    const uint32_t a_off = (uint32_t)(((mg * 32 + mrow) * SA_STRIDE + mcol) * 2);
    const int brow = (lid & 7) + (lid >> 4) * 8;
    const int bcol = ((lid >> 3) & 1) * 8;
    const uint32_t b_off = (uint32_t)(((ng * 32 + brow) * SA_STRIDE + bcol) * 2);
    const uint32_t sa_base0 = smem_u32(&sa[0][0]);
    const uint32_t sa_base1 = smem_u32(&sa[1][0]);
    const uint32_t sb_base0 = smem_u32(&sb[0][0]);
    const uint32_t sb_base1 = smem_u32(&sb[1][0]);

    float acc[2][4][4];
    #pragma unroll
    for (int mt = 0; mt < 2; mt++)
        #pragma unroll
        for (int nt = 0; nt < 4; nt++)
            #pragma unroll
            for (int r = 0; r < 4; r++) acc[mt][nt][r] = 0.f;
    float npart[8] = {0.f, 0.f, 0.f, 0.f, 0.f, 0.f, 0.f, 0.f};

    float4 ra[8];
    uint4  rb[2];

    auto ldg_chunk = [&](int c) {
        const int k0c = c * KCH;
        #pragma unroll
        for (int i = 0; i < 8; i++) {
            int id  = tid + 256 * i;
            int row = id >> 4;
            int j   = id & 15;
            long n  = n0 + row;
            ra[i] = (n < N_FEAT) ? *(const float4*)&ff[n * (long)DIM + k0c + 4 * j]
                                 : make_float4(0.f, 0.f, 0.f, 0.f);
        }
        #pragma unroll
        for (int i = 0; i < 2; i++) {
            int id  = tid + 256 * i;
            int row = id >> 3;
            int j   = id & 7;
            rb[i] = *(const uint4*)&g_qb[row * DIM + k0c + 8 * j];
        }
    };
    auto sts_chunk = [&](int buf) {
        #pragma unroll
        for (int i = 0; i < 8; i++) {
            int id  = tid + 256 * i;
            int row = id >> 4;
            int j   = id & 15;
            float4 v = ra[i];
            npart[i] = fmaf(v.x, v.x, fmaf(v.y, v.y, fmaf(v.z, v.z, fmaf(v.w, v.w, npart[i]))));
            __nv_bfloat162 p0 = __float22bfloat162_rn(make_float2(v.x, v.y));
            __nv_bfloat162 p1 = __float22bfloat162_rn(make_float2(v.z, v.w));
            *(uint2*)&sa[buf][row * SA_STRIDE + 4 * j] =
                make_uint2(*(uint32_t*)&p0, *(uint32_t*)&p1);
        }
        #pragma unroll
        for (int i = 0; i < 2; i++) {
            int id  = tid + 256 * i;
            int row = id >> 3;
            int j   = id & 7;
            *(uint4*)&sb[buf][row * SA_STRIDE + 8 * j] = rb[i];
        }
    };

    ldg_chunk(0);
    sts_chunk(0);
    if (NCHUNK > 1) ldg_chunk(1);
    __syncthreads();

    for (int c = 0; c < NCHUNK; c++) {
        if (c + 1 < NCHUNK) {
            sts_chunk((c + 1) & 1);
            if (c + 2 < NCHUNK) ldg_chunk(c + 2);
        }
        // NOTE: no sync here (R17). MMA(c) reads buf[c&1]; the STS above
        // wrote buf[(c+1)&1] — disjoint. End-sync below covers the WAR.
        const uint32_t sabuf = (c & 1) ? sa_base1 : sa_base0;
        const uint32_t sbbuf = (c & 1) ? sb_base1 : sb_base0;

        #pragma unroll
        for (int ks = 0; ks < 4; ks++) {
            uint32_t a0[4], a1[4], b0[4], b1[4];
            ldmatrix_x4(a0[0], a0[1], a0[2], a0[3], sabuf + a_off + ks * 32);
            ldmatrix_x4(a1[0], a1[1], a1[2], a1[3], sabuf + a_off + 2304u + ks * 32);
            ldmatrix_x4(b0[0], b0[1], b0[2], b0[3], sbbuf + b_off + ks * 32);
            ldmatrix_x4(b1[0], b1[1], b1[2], b1[3], sbbuf + b_off + 2304u + ks * 32);
            #pragma unroll
            for (int mt = 0; mt < 2; mt++) {
                uint32_t* a = mt ? a1 : a0;
                mma16816(acc[mt][0][0], acc[mt][0][1], acc[mt][0][2], acc[mt][0][3],
                         a[0], a[1], a[2], a[3], b0[0], b0[1]);
                mma16816(acc[mt][1][0], acc[mt][1][1], acc[mt][1][2], acc[mt][1][3],
                         a[0], a[1], a[2], a[3], b0[2], b0[3]);
                mma16816(acc[mt][2][0], acc[mt][2][1], acc[mt][2][2], acc[mt][2][3],
                         a[0], a[1], a[2], a[3], b1[0], b1[1]);
                mma16816(acc[mt][3][0], acc[mt][3][1], acc[mt][3][2], acc[mt][3][3],
                         a[0], a[1], a[2], a[3], b1[2], b1[3]);
            }
        }
        __syncthreads();
    }

    #pragma unroll
    for (int i = 0; i < 8; i++) {
        float v = npart[i];
        v += __shfl_xor_sync(0xffffffffu, v, 1);
        v += __shfl_xor_sync(0xffffffffu, v, 2);
        v += __shfl_xor_sync(0xffffffffu, v, 4);
        v += __shfl_xor_sync(0xffffffffu, v, 8);
        if ((tid & 15) == 0) snrm[(tid >> 4) + 16 * i] = v;
    }
    __syncthreads();

    {
        float s[2][2];
        bool  ok[2][2];
        #pragma unroll
        for (int mt = 0; mt < 2; mt++) {
            int r0 = mg * 32 + mt * 16 + g;
            float nr0 = snrm[r0], nr1 = snrm[r0 + 8];
            s[mt][0] = (nr0 > 0.f) ? rsqrtf(nr0) : 0.f;
            s[mt][1] = (nr1 > 0.f) ? rsqrtf(nr1) : 0.f;
            ok[mt][0] = (n0 + r0)     < N_FEAT;
            ok[mt][1] = (n0 + r0 + 8) < N_FEAT;
        }
        #pragma unroll
        for (int nt = 0; nt < 4; nt++) {
            float v0 = -CUDART_INF_F, v1 = -CUDART_INF_F;
            #pragma unroll
            for (int mt = 0; mt < 2; mt++) {
                v0 = fmaxf(v0, fmaxf(ok[mt][0] ? acc[mt][nt][0] * s[mt][0] : -CUDART_INF_F,
                                     ok[mt][1] ? acc[mt][nt][2] * s[mt][1] : -CUDART_INF_F));
                v1 = fmaxf(v1, fmaxf(ok[mt][0] ? acc[mt][nt][1] * s[mt][0] : -CUDART_INF_F,
                                     ok[mt][1] ? acc[mt][nt][3] * s[mt][1] : -CUDART_INF_F));
            }
            #pragma unroll
            for (int off = 4; off <= 16; off <<= 1) {
                v0 = fmaxf(v0, __shfl_xor_sync(0xffffffffu, v0, off));
                v1 = fmaxf(v1, __shfl_xor_sync(0xffffffffu, v1, off));
            }
            if (g == 0) {
                int q = ng * 32 + nt * 8 + 2 * tg;
                swmax[mg * NQ + q]     = v0;
                swmax[mg * NQ + q + 1] = v1;
            }
        }
    }
    __syncthreads();
    if (tid < 4 * NQ) {
        int q  = tid >> 2;
        int m4 = tid & 3;
        g_bmax[(size_t)q * NSUB + blockIdx.x * 4 + m4] = swmax[m4 * NQ + q];
    }
}

// ---------------------------------------------------------------------------
// k2: per query, top-8 subblocks — one pass (UNCHANGED from R16).
// ---------------------------------------------------------------------------
__device__ __forceinline__ void insert8(float v, int idx, float tv[NSEL], int ti[NSEL]) {
    if (better(v, idx, tv[NSEL - 1], ti[NSEL - 1])) {
        tv[NSEL - 1] = v; ti[NSEL - 1] = idx;
        #pragma unroll
        for (int s = NSEL - 1; s > 0; s--) {
            if (better(tv[s], ti[s], tv[s - 1], ti[s - 1])) {
                float fv = tv[s]; tv[s] = tv[s - 1]; tv[s - 1] = fv;
                int   fi = ti[s]; ti[s] = ti[s - 1]; ti[s - 1] = fi;
            }
        }
    }
}

__global__ __launch_bounds__(256)
void select_kernel() {
    const int q   = blockIdx.x;
    const int tid = threadIdx.x;

    float tv[NSEL]; int ti[NSEL];
    #pragma unroll
    for (int s = 0; s < NSEL; s++) { tv[s] = -CUDART_INF_F; ti[s] = 0x7fffffff; }

    const float* row = &g_bmax[(size_t)q * NSUB];
    for (int b = tid; b < NSUB; b += 256)
        insert8(row[b], b, tv, ti);

    __shared__ float sv[256 * NSEL];
    __shared__ int   si[256 * NSEL];
    #pragma unroll
    for (int s = 0; s < NSEL; s++) { sv[tid * NSEL + s] = tv[s]; si[tid * NSEL + s] = ti[s]; }
    __syncthreads();

    for (int off = 128; off >= 1; off >>= 1) {
        if (tid < off) {
            float ov[NSEL]; int oi[NSEL];
            #pragma unroll
            for (int s = 0; s < NSEL; s++) {
                ov[s] = sv[(tid + off) * NSEL + s];
                oi[s] = si[(tid + off) * NSEL + s];
            }
            float mv[NSEL]; int mi[NSEL];
            int a = 0, b = 0;
            #pragma unroll
            for (int o = 0; o < NSEL; o++) {
                if (better(tv[a], ti[a], ov[b], oi[b])) { mv[o] = tv[a]; mi[o] = ti[a]; a++; }
                else                                    { mv[o] = ov[b]; mi[o] = oi[b]; b++; }
            }
            #pragma unroll
            for (int s = 0; s < NSEL; s++) {
                tv[s] = mv[s]; ti[s] = mi[s];
                sv[tid * NSEL + s] = mv[s];
                si[tid * NSEL + s] = mi[s];
            }
        }
        __syncthreads();
    }

    if (tid == 0) {
        #pragma unroll
        for (int s = 0; s < NSEL; s++) g_selblk[q * NSEL + s] = ti[s];
    }
}

// ---------------------------------------------------------------------------
// k3: exact fp32 rescore — R17: ONE ROW PER WARP (32 warps = whole subblock
// in one parallel pass; removes the 4-deep serial row chain, issue was 16%).
// ---------------------------------------------------------------------------
__device__ __forceinline__ void insert5(float v, int idx, float tv[5], int ti[5]) {
    if (better(v, idx, tv[4], ti[4])) {
        tv[4] = v; ti[4] = idx;
        #pragma unroll
        for (int s = 4; s > 0; s--) {
            if (better(tv[s], ti[s], tv[s - 1], ti[s - 1])) {
                float fv = tv[s]; tv[s] = tv[s - 1]; tv[s - 1] = fv;
                int   fi = ti[s]; ti[s] = ti[s - 1]; ti[s - 1] = fi;
            }
        }
    }
}

__global__ __launch_bounds__(1024)
void rescore_kernel(const float* __restrict__ qf, const float* __restrict__ ff) {
    __shared__ float swv[32]; __shared__ int swi[32];

    const int b    = blockIdx.x;        // 0..NQ*NSEL-1
    const int q    = b >> 3;
    const int slot = b & (NSEL - 1);
    const int wid  = threadIdx.x >> 5;  // 0..31 = row within subblock
    const int lid  = threadIdx.x & 31;

    const long row = (long)g_selblk[q * NSEL + slot] * SUB + wid;

    float val = -CUDART_INF_F; int idx = 0x7fffffff;
    if (row < N_FEAT) {
        const float4* fr = (const float4*)&ff[row * (long)DIM];
        const float4* qr = (const float4*)&qf[q * DIM];
        float dot = 0.f, nr = 0.f;
        #pragma unroll
        for (int u = 0; u < 6; u++) {
            float4 a = fr[lid + 32 * u];
            float4 bq = qr[lid + 32 * u];
            dot = fmaf(a.x, bq.x, fmaf(a.y, bq.y, fmaf(a.z, bq.z, fmaf(a.w, bq.w, dot))));
            nr  = fmaf(a.x, a.x, fmaf(a.y, a.y, fmaf(a.z, a.z, fmaf(a.w, a.w, nr))));
        }
        #pragma unroll
        for (int off = 16; off >= 1; off >>= 1) {
            dot += __shfl_xor_sync(0xffffffffu, dot, off);
            nr  += __shfl_xor_sync(0xffffffffu, nr,  off);
        }
        val = dot * rsqrtf(nr);
        idx = (int)row;
    }
    if (lid == 0) { swv[wid] = val; swi[wid] = idx; }
    __syncthreads();

    if (threadIdx.x == 0) {
        float mv[TOPK]; int mi[TOPK];
        #pragma unroll
        for (int s = 0; s < TOPK; s++) { mv[s] = -CUDART_INF_F; mi[s] = 0x7fffffff; }
        for (int w = 0; w < 32; w++)
            insert5(swv[w], swi[w], mv, mi);
        #pragma unroll
        for (int s = 0; s < TOPK; s++) {
            g_cv[b * TOPK + s] = mv[s];
            g_ci[b * TOPK + s] = mi[s];
        }
    }
}

// ---------------------------------------------------------------------------
// k4: gather with inlined final top-5 (UNCHANGED from R16).
// ---------------------------------------------------------------------------
__global__ __launch_bounds__(128)
void gather_kernel(const int* __restrict__ data, float* __restrict__ out) {
    __shared__ int s_idx;
    const int r = blockIdx.x;
    const int q = r / TOPK;
    const int j = r % TOPK;

    if (threadIdx.x == 0) {
        float tv[TOPK]; int ti[TOPK];
        #pragma unroll
        for (int s = 0; s < TOPK; s++) { tv[s] = -CUDART_INF_F; ti[s] = 0x7fffffff; }
        for (int e = 0; e < NSEL * TOPK; e++)
            insert5(g_cv[q * NSEL * TOPK + e], g_ci[q * NSEL * TOPK + e], tv, ti);
        int idx = ti[j];
        s_idx = (idx < 0) ? 0 : ((idx >= N_FEAT) ? N_FEAT - 1 : idx);
    }
    __syncthreads();

    const int idx = s_idx;
    const int4* src = (const int4*)&data[(size_t)idx * SEGLEN];
    float4* dst = (float4*)&out[(size_t)r * SEGLEN];
    for (int t = threadIdx.x; t < SEGLEN / 4; t += blockDim.x) {
        int4 v = src[t];
        dst[t] = make_float4((float)v.x, (float)v.y, (float)v.z, (float)v.w);
    }
}

// ---------------------------------------------------------------------------
extern "C" void kernel_launch(void* const* d_in, const int* in_sizes, int n_in,
                              void* d_out, int out_size) {
    (void)out_size;
    int i_ff = 0, i_dt = -1, i_qf = -1;
    for (int i = 1; i < n_in; i++)
        if ((unsigned)in_sizes[i] > (unsigned)in_sizes[i_ff]) i_ff = i;
    for (int i = 0; i < n_in; i++) {
        if (i == i_ff) continue;
        if (i_dt < 0 || (unsigned)in_sizes[i] > (unsigned)in_sizes[i_dt]) i_dt = i;
    }
    for (int i = 0; i < n_in; i++) {
        if (i == i_ff || i == i_dt) continue;
        if (i_qf < 0 || (unsigned)in_sizes[i] > (unsigned)in_sizes[i_qf]) i_qf = i;
    }
    const float* qf   = (const float*)d_in[i_qf >= 0 ? i_qf : 0];
    const float* ff   = (const float*)d_in[i_ff];
    const int*   data = (const int*)d_in[i_dt >= 0 ? i_dt : (n_in > 2 ? 2 : 0)];
    float* out = (float*)d_out;

    qconv_kernel<<<(NQ * DIM / 2 + 255) / 256, 256>>>(qf);
    mma_score_kernel<<<NBLK, 256>>>(ff);
    select_kernel<<<NQ, 256>>>();
    rescore_kernel<<<NQ * NSEL, 1024>>>(qf, ff);
    gather_kernel<<<NQ * TOPK, 128>>>(data, out);
}